// round 8
// baseline (speedup 1.0000x reference)
#include <cuda_runtime.h>
#include <math.h>

#define NMAX 50000
#define EMAX 800000
#define DMAX 128

// Scratch (device globals; no allocation in kernel_launch)
__device__ float g_hs[NMAX * DMAX];    // hs = (x@W) * dis[row]
__device__ float g_x[NMAX * DMAX];     // layer activations
__device__ float g_dis[NMAX];          // rsqrt(deg+1)
__device__ float g_s[NMAX];            // node scores
__device__ int   g_counts[NMAX];       // in-degree histogram
__device__ int   g_offsets[NMAX + 1];  // CSR row offsets
__device__ int   g_cursor[NMAX];       // fill cursors
__device__ int   g_csr[EMAX];          // CSR src indices grouped by dst
__device__ int   g_bsums[256];         // scan block partials

// ---------------------------------------------------------------------------
// f32x2 packed-FMA helpers (sm_103a dual fp32 path)
__device__ __forceinline__ unsigned long long pack2(float x) {
    unsigned long long r;
    asm("mov.b64 %0, {%1, %1};" : "=l"(r) : "f"(x));
    return r;
}
__device__ __forceinline__ void fma2(unsigned long long& d,
                                     unsigned long long a,
                                     unsigned long long b) {
    asm("fma.rn.f32x2 %0, %1, %2, %3;" : "=l"(d) : "l"(a), "l"(b), "l"(d));
}
__device__ __forceinline__ float2 unpack2(unsigned long long v) {
    float2 f;
    asm("mov.b64 {%0, %1}, %2;" : "=f"(f.x), "=f"(f.y) : "l"(v));
    return f;
}

// ---------------------------------------------------------------------------
// Histogram, 4 edges per thread (int4) for MLP
__global__ void hist_kernel(const int* __restrict__ dst, int E, int* counts) {
    int i = blockIdx.x * blockDim.x + threadIdx.x;
    int E4 = E >> 2;
    if (i < E4) {
        int4 d = ((const int4*)dst)[i];
        atomicAdd(&counts[d.x], 1);
        atomicAdd(&counts[d.y], 1);
        atomicAdd(&counts[d.z], 1);
        atomicAdd(&counts[d.w], 1);
    }
    // tail
    int t = E4 * 4 + i;
    if (i < (E & 3)) atomicAdd(&counts[dst[t]], 1);
}

// Two-level exclusive scan: (1) per-block sums, (2) scan partials, (3) write.
__global__ void blocksum_kernel(const int* __restrict__ counts, int* bsums, int n) {
    __shared__ int sh[256];
    int i = blockIdx.x * 256 + threadIdx.x;
    sh[threadIdx.x] = (i < n) ? counts[i] : 0;
    __syncthreads();
#pragma unroll
    for (int off = 128; off > 0; off >>= 1) {
        if (threadIdx.x < off) sh[threadIdx.x] += sh[threadIdx.x + off];
        __syncthreads();
    }
    if (threadIdx.x == 0) bsums[blockIdx.x] = sh[0];
}

__global__ void scan_bsums_kernel(int* bsums, int nb, int* offsets, int n) {
    __shared__ int sh[256];
    int t = threadIdx.x;
    int v = (t < nb) ? bsums[t] : 0;
    sh[t] = v;
    __syncthreads();
#pragma unroll
    for (int off = 1; off < 256; off <<= 1) {
        int u = (t >= off) ? sh[t - off] : 0;
        __syncthreads();
        sh[t] += u;
        __syncthreads();
    }
    if (t < nb) bsums[t] = sh[t] - v;  // exclusive
    if (t == 255) offsets[n] = sh[255];
}

__global__ void offsets_kernel(const int* __restrict__ counts,
                               const int* __restrict__ bsums,
                               int* offsets, int* cursor, float* dis, int n) {
    __shared__ int sh[256];
    int t = threadIdx.x;
    int i = blockIdx.x * 256 + t;
    int v = (i < n) ? counts[i] : 0;
    sh[t] = v;
    __syncthreads();
#pragma unroll
    for (int off = 1; off < 256; off <<= 1) {
        int u = (t >= off) ? sh[t - off] : 0;
        __syncthreads();
        sh[t] += u;
        __syncthreads();
    }
    if (i < n) {
        int o = bsums[blockIdx.x] + sh[t] - v;
        offsets[i] = o;
        cursor[i] = o;
        dis[i] = rsqrtf((float)v + 1.0f);
    }
}

// CSR fill, 4 edges per thread
__global__ void fill_kernel(const int* __restrict__ src,
                            const int* __restrict__ dst, int E,
                            int* cursor, int* __restrict__ csr) {
    int i = blockIdx.x * blockDim.x + threadIdx.x;
    int E4 = E >> 2;
    if (i < E4) {
        int4 s = ((const int4*)src)[i];
        int4 d = ((const int4*)dst)[i];
        int p0 = atomicAdd(&cursor[d.x], 1);
        int p1 = atomicAdd(&cursor[d.y], 1);
        int p2 = atomicAdd(&cursor[d.z], 1);
        int p3 = atomicAdd(&cursor[d.w], 1);
        csr[p0] = s.x;
        csr[p1] = s.y;
        csr[p2] = s.z;
        csr[p3] = s.w;
    }
    int t = E4 * 4 + i;
    if (i < (E & 3)) {
        int pos = atomicAdd(&cursor[dst[t]], 1);
        csr[pos] = src[t];
    }
}

// ---------------------------------------------------------------------------
// Register-blocked SGEMM + row scale using packed f32x2 FMAs.
// out[r, c] = (A@W)[r, c] * dis[r].  BM=128 rows/block, 256 threads.
template <int DIN, int DOUT>
__global__ void gemm_scale_kernel(const float* __restrict__ A,
                                  const float* __restrict__ W,
                                  const float* __restrict__ dis,
                                  float* __restrict__ out, int n) {
    constexpr int BM = 128, BK = 8, TN = 8;
    constexpr int TX = DOUT / TN;   // 16 / 8 / 4
    constexpr int TY = 256 / TX;    // 16 / 32 / 64
    constexpr int TM = BM / TY;     // 8 / 4 / 2

    __shared__ float As[BK][BM + 4];
    __shared__ float Ws[BK][DOUT];

    int tid = threadIdx.x;
    int tx = tid % TX, ty = tid / TX;
    int row0 = blockIdx.x * BM;

    unsigned long long acc[TM][TN / 2] = {};  // bits 0 == {0.f, 0.f}

    for (int k0 = 0; k0 < DIN; k0 += BK) {
        // A tile: 128 rows x 8 k; one float4 per thread, stored k-major
        {
            int r = tid >> 1;
            int kk = (tid & 1) * 4;
            int grow = row0 + r;
            float4 v = make_float4(0.f, 0.f, 0.f, 0.f);
            if (grow < n) v = *(const float4*)&A[grow * DIN + k0 + kk];
            As[kk][r] = v.x;
            As[kk + 1][r] = v.y;
            As[kk + 2][r] = v.z;
            As[kk + 3][r] = v.w;
        }
        // W tile: rows k0..k0+7 are contiguous in W
        {
            const float4* wsrc = (const float4*)(W + k0 * DOUT);
            float4* wdst = (float4*)&Ws[0][0];
#pragma unroll
            for (int i = tid; i < BK * DOUT / 4; i += 256) wdst[i] = wsrc[i];
        }
        __syncthreads();

#pragma unroll
        for (int k = 0; k < BK; k++) {
            unsigned long long b2[TN / 2];
            const unsigned long long* wp =
                (const unsigned long long*)&Ws[k][tx * TN];
#pragma unroll
            for (int j = 0; j < TN / 2; j++) b2[j] = wp[j];
#pragma unroll
            for (int i = 0; i < TM; i++) {
                unsigned long long rp = pack2(As[k][ty * TM + i]);
#pragma unroll
                for (int j = 0; j < TN / 2; j++) fma2(acc[i][j], rp, b2[j]);
            }
        }
        __syncthreads();
    }

#pragma unroll
    for (int i = 0; i < TM; i++) {
        int r = row0 + ty * TM + i;
        if (r < n) {
            float dv = dis[r];
            float2 p0 = unpack2(acc[i][0]);
            float2 p1 = unpack2(acc[i][1]);
            float2 p2 = unpack2(acc[i][2]);
            float2 p3 = unpack2(acc[i][3]);
            float4 o0 = make_float4(p0.x * dv, p0.y * dv, p1.x * dv, p1.y * dv);
            float4 o1 = make_float4(p2.x * dv, p2.y * dv, p3.x * dv, p3.y * dv);
            float* op = &out[r * DOUT + tx * TN];
            *(float4*)op = o0;
            *(float4*)(op + 4) = o1;
        }
    }
}

// ---------------------------------------------------------------------------
template <int VW>
__device__ __forceinline__ void vload_add(const float* __restrict__ p, float* a) {
    if constexpr (VW == 4) {
        float4 t = *(const float4*)p;
        a[0] += t.x; a[1] += t.y; a[2] += t.z; a[3] += t.w;
    } else if constexpr (VW == 2) {
        float2 t = *(const float2*)p;
        a[0] += t.x; a[1] += t.y;
    } else {
        a[0] += *p;
    }
}

// One warp per node, edge loop unrolled x8 with 4 independent accumulators.
// acc = sum over in-edges of hs[src]; out = relu(dis[v]*(acc + hs[v]) + b)
template <int DOUT>
__global__ void __launch_bounds__(256)
gather_combine_kernel(const float* __restrict__ hs,
                      const int* __restrict__ csr,
                      const int* __restrict__ offsets,
                      const float* __restrict__ b,
                      const float* __restrict__ dis,
                      float* __restrict__ out, int n) {
    constexpr int VW = DOUT / 32;  // 4 / 2 floats per lane
    int warp = (blockIdx.x * blockDim.x + threadIdx.x) >> 5;
    int lane = threadIdx.x & 31;
    if (warp >= n) return;
    int v = warp;
    int s0 = offsets[v], s1 = offsets[v + 1];

    float a0[VW] = {}, a1[VW] = {}, a2[VW] = {}, a3[VW] = {};
    int fo = lane * VW;
    const float* __restrict__ base = hs + fo;

    int e = s0;
    for (; e + 8 <= s1; e += 8) {
        int i0 = __ldg(&csr[e]);
        int i1 = __ldg(&csr[e + 1]);
        int i2 = __ldg(&csr[e + 2]);
        int i3 = __ldg(&csr[e + 3]);
        int i4 = __ldg(&csr[e + 4]);
        int i5 = __ldg(&csr[e + 5]);
        int i6 = __ldg(&csr[e + 6]);
        int i7 = __ldg(&csr[e + 7]);
        vload_add<VW>(base + (size_t)i0 * DOUT, a0);
        vload_add<VW>(base + (size_t)i1 * DOUT, a1);
        vload_add<VW>(base + (size_t)i2 * DOUT, a2);
        vload_add<VW>(base + (size_t)i3 * DOUT, a3);
        vload_add<VW>(base + (size_t)i4 * DOUT, a0);
        vload_add<VW>(base + (size_t)i5 * DOUT, a1);
        vload_add<VW>(base + (size_t)i6 * DOUT, a2);
        vload_add<VW>(base + (size_t)i7 * DOUT, a3);
    }
    for (; e + 2 <= s1; e += 2) {
        int i0 = __ldg(&csr[e]);
        int i1 = __ldg(&csr[e + 1]);
        vload_add<VW>(base + (size_t)i0 * DOUT, a0);
        vload_add<VW>(base + (size_t)i1 * DOUT, a1);
    }
    if (e < s1) {
        int i0 = __ldg(&csr[e]);
        vload_add<VW>(base + (size_t)i0 * DOUT, a2);
    }

    float dv = dis[v];
    const float* hp = hs + (size_t)v * DOUT + fo;
    float* op = out + (size_t)v * DOUT + fo;
#pragma unroll
    for (int j = 0; j < VW; j++) {
        float r = dv * ((a0[j] + a1[j]) + (a2[j] + a3[j]) + hp[j]) + b[fo + j];
        op[j] = r > 0.0f ? r : 0.0f;
    }
}

// ---------------------------------------------------------------------------
// Layer-2 gather (DOUT=32, VW=1) fused with the MLP head:
// x(32) -> relu(16) -> relu(8) -> sigmoid(1), all in-warp via shuffles.
__global__ void __launch_bounds__(256)
gather_combine_mlp_kernel(const float* __restrict__ hs,
                          const int* __restrict__ csr,
                          const int* __restrict__ offsets,
                          const float* __restrict__ b,
                          const float* __restrict__ dis,
                          const float* __restrict__ lw0, const float* __restrict__ lb0,
                          const float* __restrict__ lw1, const float* __restrict__ lb1,
                          const float* __restrict__ lw2, const float* __restrict__ lb2,
                          float* __restrict__ s, int n) {
    __shared__ float w0[32 * 16], b0s[16], w1[16 * 8], b1s[8], w2s[8], b2s[1];
    {
        int t = threadIdx.x;
        for (int j = t; j < 32 * 16; j += blockDim.x) w0[j] = lw0[j];
        for (int j = t; j < 16; j += blockDim.x) b0s[j] = lb0[j];
        for (int j = t; j < 16 * 8; j += blockDim.x) w1[j] = lw1[j];
        for (int j = t; j < 8; j += blockDim.x) b1s[j] = lb1[j];
        for (int j = t; j < 8; j += blockDim.x) w2s[j] = lw2[j];
        if (t == 0) b2s[0] = lb2[0];
    }
    __syncthreads();

    int warp = (blockIdx.x * blockDim.x + threadIdx.x) >> 5;
    int lane = threadIdx.x & 31;
    if (warp >= n) return;
    int v = warp;
    int s0 = offsets[v], s1 = offsets[v + 1];

    float a0 = 0.f, a1 = 0.f, a2 = 0.f, a3 = 0.f;
    const float* __restrict__ base = hs + lane;

    int e = s0;
    for (; e + 8 <= s1; e += 8) {
        int i0 = __ldg(&csr[e]);
        int i1 = __ldg(&csr[e + 1]);
        int i2 = __ldg(&csr[e + 2]);
        int i3 = __ldg(&csr[e + 3]);
        int i4 = __ldg(&csr[e + 4]);
        int i5 = __ldg(&csr[e + 5]);
        int i6 = __ldg(&csr[e + 6]);
        int i7 = __ldg(&csr[e + 7]);
        a0 += base[(size_t)i0 * 32];
        a1 += base[(size_t)i1 * 32];
        a2 += base[(size_t)i2 * 32];
        a3 += base[(size_t)i3 * 32];
        a0 += base[(size_t)i4 * 32];
        a1 += base[(size_t)i5 * 32];
        a2 += base[(size_t)i6 * 32];
        a3 += base[(size_t)i7 * 32];
    }
    for (; e + 2 <= s1; e += 2) {
        int i0 = __ldg(&csr[e]);
        int i1 = __ldg(&csr[e + 1]);
        a0 += base[(size_t)i0 * 32];
        a1 += base[(size_t)i1 * 32];
    }
    if (e < s1) {
        int i0 = __ldg(&csr[e]);
        a2 += base[(size_t)i0 * 32];
    }

    float dv = dis[v];
    float hv = hs[(size_t)v * 32 + lane];
    float xf = dv * ((a0 + a1) + (a2 + a3) + hv) + b[lane];
    xf = xf > 0.0f ? xf : 0.0f;  // node feature `lane`

    // MLP layer 1: lanes 0..15 own output j = lane
    float y1 = (lane < 16) ? b0s[lane] : 0.0f;
#pragma unroll
    for (int k = 0; k < 32; k++) {
        float xk = __shfl_sync(0xffffffffu, xf, k);
        if (lane < 16) y1 += xk * w0[k * 16 + lane];
    }
    y1 = y1 > 0.0f ? y1 : 0.0f;

    // MLP layer 2: lanes 0..7 own output j = lane
    float y2 = (lane < 8) ? b1s[lane] : 0.0f;
#pragma unroll
    for (int k = 0; k < 16; k++) {
        float yk = __shfl_sync(0xffffffffu, y1, k);
        if (lane < 8) y2 += yk * w1[k * 8 + lane];
    }
    y2 = y2 > 0.0f ? y2 : 0.0f;

    // MLP layer 3: dot over 8 lanes + sigmoid
    float z = (lane < 8) ? y2 * w2s[lane] : 0.0f;
    z += __shfl_xor_sync(0xffffffffu, z, 4);
    z += __shfl_xor_sync(0xffffffffu, z, 2);
    z += __shfl_xor_sync(0xffffffffu, z, 1);
    if (lane == 0) s[v] = 1.0f / (1.0f + expf(-(z + b2s[0])));
}

__global__ void edge_score_kernel(const int* __restrict__ pe,
                                  const float* __restrict__ s,
                                  float* __restrict__ out, int ep) {
    int i = blockIdx.x * blockDim.x + threadIdx.x;
    if (i < ep) {
        int2 p = ((const int2*)pe)[i];
        out[i] = s[p.x] * s[p.y];
    }
}

// ---------------------------------------------------------------------------
extern "C" void kernel_launch(void* const* d_in, const int* in_sizes, int n_in,
                              void* d_out, int out_size) {
    const float* x   = (const float*)d_in[0];
    const int* ei    = (const int*)d_in[1];
    const int* pe    = (const int*)d_in[2];
    const float* cw0 = (const float*)d_in[3];
    const float* cb0 = (const float*)d_in[4];
    const float* cw1 = (const float*)d_in[5];
    const float* cb1 = (const float*)d_in[6];
    const float* cw2 = (const float*)d_in[7];
    const float* cb2 = (const float*)d_in[8];
    const float* lw0 = (const float*)d_in[9];
    const float* lb0 = (const float*)d_in[10];
    const float* lw1 = (const float*)d_in[11];
    const float* lb1 = (const float*)d_in[12];
    const float* lw2 = (const float*)d_in[13];
    const float* lb2 = (const float*)d_in[14];
    float* out = (float*)d_out;

    const int N  = in_sizes[0] / 128;
    const int E  = in_sizes[1] / 2;
    const int EP = out_size;

    const int* src = ei;
    const int* dst = ei + E;

    float *hs, *xb, *dis, *sc;
    int *counts, *offsets, *cursor, *csr, *bsums;
    cudaGetSymbolAddress((void**)&hs, g_hs);
    cudaGetSymbolAddress((void**)&xb, g_x);
    cudaGetSymbolAddress((void**)&dis, g_dis);
    cudaGetSymbolAddress((void**)&sc, g_s);
    cudaGetSymbolAddress((void**)&counts, g_counts);
    cudaGetSymbolAddress((void**)&offsets, g_offsets);
    cudaGetSymbolAddress((void**)&cursor, g_cursor);
    cudaGetSymbolAddress((void**)&csr, g_csr);
    cudaGetSymbolAddress((void**)&bsums, g_bsums);

    const int B = 256;
    const int NB = (N + 255) / 256;  // scan blocks (<= 256)
    const int E4 = (E + 3) / 4;

    // CSR build + dis (shared by all 3 conv layers)
    cudaMemsetAsync(counts, 0, N * sizeof(int));
    hist_kernel<<<(E4 + B - 1) / B, B>>>(dst, E, counts);
    blocksum_kernel<<<NB, 256>>>(counts, bsums, N);
    scan_bsums_kernel<<<1, 256>>>(bsums, NB, offsets, N);
    offsets_kernel<<<NB, 256>>>(counts, bsums, offsets, cursor, dis, N);
    fill_kernel<<<(E4 + B - 1) / B, B>>>(src, dst, E, cursor, csr);

    int gwarp = (N * 32 + B - 1) / B;  // 1 warp per node

    // Layer 0: 128 -> 128
    gemm_scale_kernel<128, 128><<<(N + 127) / 128, 256>>>(x, cw0, dis, hs, N);
    gather_combine_kernel<128><<<gwarp, B>>>(hs, csr, offsets, cb0, dis, xb, N);
    // Layer 1: 128 -> 64
    gemm_scale_kernel<128, 64><<<(N + 127) / 128, 256>>>(xb, cw1, dis, hs, N);
    gather_combine_kernel<64><<<gwarp, B>>>(hs, csr, offsets, cb1, dis, xb, N);
    // Layer 2: 64 -> 32, gather fused with MLP head -> node scores
    gemm_scale_kernel<64, 32><<<(N + 127) / 128, 256>>>(xb, cw2, dis, hs, N);
    gather_combine_mlp_kernel<<<gwarp, B>>>(hs, csr, offsets, cb2, dis,
                                            lw0, lb0, lw1, lb1, lw2, lb2, sc, N);

    edge_score_kernel<<<(EP + B - 1) / B, B>>>(pe, sc, out, EP);
}

// round 11
// speedup vs baseline: 1.0634x; 1.0634x over previous
#include <cuda_runtime.h>
#include <math.h>

#define NMAX 50000
#define EMAX 800000
#define DMAX 128

// Scratch (device globals; no allocation in kernel_launch)
__device__ float g_hs[NMAX * DMAX];    // h (= x@W), scaled or not per layer
__device__ float g_x[NMAX * DMAX];     // layer activations
__device__ float g_dis[NMAX];          // rsqrt(deg+1)
__device__ float g_s[NMAX];            // node scores
__device__ int   g_counts[NMAX];       // in-degree histogram
__device__ int   g_offsets[NMAX + 1];  // CSR row offsets
__device__ int   g_cursor[NMAX];       // fill cursors
__device__ int   g_csr[EMAX];          // CSR src indices grouped by dst
__device__ int   g_bsums[256];         // scan block partials

// ---------------------------------------------------------------------------
// f32x2 packed-FMA helpers (sm_103a dual fp32 path)
__device__ __forceinline__ unsigned long long pack2(float x) {
    unsigned long long r;
    asm("mov.b64 %0, {%1, %1};" : "=l"(r) : "f"(x));
    return r;
}
__device__ __forceinline__ void fma2(unsigned long long& d,
                                     unsigned long long a,
                                     unsigned long long b) {
    asm("fma.rn.f32x2 %0, %1, %2, %3;" : "=l"(d) : "l"(a), "l"(b), "l"(d));
}
__device__ __forceinline__ float2 unpack2(unsigned long long v) {
    float2 f;
    asm("mov.b64 {%0, %1}, %2;" : "=f"(f.x), "=f"(f.y) : "l"(v));
    return f;
}

// ---------------------------------------------------------------------------
// Histogram, 4 edges per thread (int4) for MLP
__global__ void hist_kernel(const int* __restrict__ dst, int E, int* counts) {
    int i = blockIdx.x * blockDim.x + threadIdx.x;
    int E4 = E >> 2;
    if (i < E4) {
        int4 d = ((const int4*)dst)[i];
        atomicAdd(&counts[d.x], 1);
        atomicAdd(&counts[d.y], 1);
        atomicAdd(&counts[d.z], 1);
        atomicAdd(&counts[d.w], 1);
    }
    int t = E4 * 4 + i;
    if (i < (E & 3)) atomicAdd(&counts[dst[t]], 1);
}

// Two-level exclusive scan
__global__ void blocksum_kernel(const int* __restrict__ counts, int* bsums, int n) {
    __shared__ int sh[256];
    int i = blockIdx.x * 256 + threadIdx.x;
    sh[threadIdx.x] = (i < n) ? counts[i] : 0;
    __syncthreads();
#pragma unroll
    for (int off = 128; off > 0; off >>= 1) {
        if (threadIdx.x < off) sh[threadIdx.x] += sh[threadIdx.x + off];
        __syncthreads();
    }
    if (threadIdx.x == 0) bsums[blockIdx.x] = sh[0];
}

__global__ void scan_bsums_kernel(int* bsums, int nb, int* offsets, int n) {
    __shared__ int sh[256];
    int t = threadIdx.x;
    int v = (t < nb) ? bsums[t] : 0;
    sh[t] = v;
    __syncthreads();
#pragma unroll
    for (int off = 1; off < 256; off <<= 1) {
        int u = (t >= off) ? sh[t - off] : 0;
        __syncthreads();
        sh[t] += u;
        __syncthreads();
    }
    if (t < nb) bsums[t] = sh[t] - v;  // exclusive
    if (t == 255) offsets[n] = sh[255];
}

__global__ void offsets_kernel(const int* __restrict__ counts,
                               const int* __restrict__ bsums,
                               int* offsets, int* cursor, float* dis, int n) {
    __shared__ int sh[256];
    int t = threadIdx.x;
    int i = blockIdx.x * 256 + t;
    int v = (i < n) ? counts[i] : 0;
    sh[t] = v;
    __syncthreads();
#pragma unroll
    for (int off = 1; off < 256; off <<= 1) {
        int u = (t >= off) ? sh[t - off] : 0;
        __syncthreads();
        sh[t] += u;
        __syncthreads();
    }
    if (i < n) {
        int o = bsums[blockIdx.x] + sh[t] - v;
        offsets[i] = o;
        cursor[i] = o;
        dis[i] = rsqrtf((float)v + 1.0f);
    }
}

// CSR fill, 4 edges per thread
__global__ void fill_kernel(const int* __restrict__ src,
                            const int* __restrict__ dst, int E,
                            int* cursor, int* __restrict__ csr) {
    int i = blockIdx.x * blockDim.x + threadIdx.x;
    int E4 = E >> 2;
    if (i < E4) {
        int4 s = ((const int4*)src)[i];
        int4 d = ((const int4*)dst)[i];
        int p0 = atomicAdd(&cursor[d.x], 1);
        int p1 = atomicAdd(&cursor[d.y], 1);
        int p2 = atomicAdd(&cursor[d.z], 1);
        int p3 = atomicAdd(&cursor[d.w], 1);
        csr[p0] = s.x;
        csr[p1] = s.y;
        csr[p2] = s.z;
        csr[p3] = s.w;
    }
    int t = E4 * 4 + i;
    if (i < (E & 3)) {
        int pos = atomicAdd(&cursor[dst[t]], 1);
        csr[pos] = src[t];
    }
}

// ---------------------------------------------------------------------------
// Register-blocked SGEMM using packed f32x2 FMAs.
// out[r, c] = (A@W)[r, c] * (SCALE ? dis[r] : 1).  BM=128, 256 threads.
template <int DIN, int DOUT, bool SCALE>
__global__ void gemm_scale_kernel(const float* __restrict__ A,
                                  const float* __restrict__ W,
                                  const float* __restrict__ dis,
                                  float* __restrict__ out, int n) {
    constexpr int BM = 128, BK = 8, TN = 8;
    constexpr int TX = DOUT / TN;
    constexpr int TY = 256 / TX;
    constexpr int TM = BM / TY;

    __shared__ float As[BK][BM + 4];
    __shared__ float Ws[BK][DOUT];

    int tid = threadIdx.x;
    int tx = tid % TX, ty = tid / TX;
    int row0 = blockIdx.x * BM;

    unsigned long long acc[TM][TN / 2] = {};

    for (int k0 = 0; k0 < DIN; k0 += BK) {
        {
            int r = tid >> 1;
            int kk = (tid & 1) * 4;
            int grow = row0 + r;
            float4 v = make_float4(0.f, 0.f, 0.f, 0.f);
            if (grow < n) v = *(const float4*)&A[grow * DIN + k0 + kk];
            As[kk][r] = v.x;
            As[kk + 1][r] = v.y;
            As[kk + 2][r] = v.z;
            As[kk + 3][r] = v.w;
        }
        {
            const float4* wsrc = (const float4*)(W + k0 * DOUT);
            float4* wdst = (float4*)&Ws[0][0];
#pragma unroll
            for (int i = tid; i < BK * DOUT / 4; i += 256) wdst[i] = wsrc[i];
        }
        __syncthreads();

#pragma unroll
        for (int k = 0; k < BK; k++) {
            unsigned long long b2[TN / 2];
            const unsigned long long* wp =
                (const unsigned long long*)&Ws[k][tx * TN];
#pragma unroll
            for (int j = 0; j < TN / 2; j++) b2[j] = wp[j];
#pragma unroll
            for (int i = 0; i < TM; i++) {
                unsigned long long rp = pack2(As[k][ty * TM + i]);
#pragma unroll
                for (int j = 0; j < TN / 2; j++) fma2(acc[i][j], rp, b2[j]);
            }
        }
        __syncthreads();
    }

#pragma unroll
    for (int i = 0; i < TM; i++) {
        int r = row0 + ty * TM + i;
        if (r < n) {
            float dv = SCALE ? dis[r] : 1.0f;
            float2 p0 = unpack2(acc[i][0]);
            float2 p1 = unpack2(acc[i][1]);
            float2 p2 = unpack2(acc[i][2]);
            float2 p3 = unpack2(acc[i][3]);
            float4 o0 = make_float4(p0.x * dv, p0.y * dv, p1.x * dv, p1.y * dv);
            float4 o1 = make_float4(p2.x * dv, p2.y * dv, p3.x * dv, p3.y * dv);
            float* op = &out[r * DOUT + tx * TN];
            *(float4*)op = o0;
            *(float4*)(op + 4) = o1;
        }
    }
}

// ---------------------------------------------------------------------------
template <int VW>
__device__ __forceinline__ void vload_add(const float* __restrict__ p, float* a) {
    if constexpr (VW == 4) {
        float4 t = *(const float4*)p;
        a[0] += t.x; a[1] += t.y; a[2] += t.z; a[3] += t.w;
    } else if constexpr (VW == 2) {
        float2 t = *(const float2*)p;
        a[0] += t.x; a[1] += t.y;
    } else {
        a[0] += *p;
    }
}
template <int VW>
__device__ __forceinline__ void vload_fma(const float* __restrict__ p, float s,
                                          float* a) {
    if constexpr (VW == 4) {
        float4 t = *(const float4*)p;
        a[0] += t.x * s; a[1] += t.y * s; a[2] += t.z * s; a[3] += t.w * s;
    } else if constexpr (VW == 2) {
        float2 t = *(const float2*)p;
        a[0] += t.x * s; a[1] += t.y * s;
    } else {
        a[0] += *p * s;
    }
}

// One warp per node, edge loop unrolled x4, dual accumulators.
// EDGE_SCALE=false: hs already contains h*dis[row]; acc = sum hs[src];
//   out = relu(dis[v]*(acc + hs[v]) + b)
// EDGE_SCALE=true: hs contains unscaled h; acc = sum h[src]*dis[src];
//   out = relu(dis[v]*(acc + h[v]*dis[v]) + b)
template <int DOUT, bool EDGE_SCALE>
__global__ void __launch_bounds__(256)
gather_combine_kernel(const float* __restrict__ hs,
                      const int* __restrict__ csr,
                      const int* __restrict__ offsets,
                      const float* __restrict__ b,
                      const float* __restrict__ dis,
                      float* __restrict__ out, int n) {
    constexpr int VW = DOUT / 32;
    int warp = (blockIdx.x * blockDim.x + threadIdx.x) >> 5;
    int lane = threadIdx.x & 31;
    if (warp >= n) return;
    int v = warp;
    int s0 = offsets[v], s1 = offsets[v + 1];

    float acc0[VW] = {}, acc1[VW] = {};
    int fo = lane * VW;
    const float* __restrict__ base = hs + fo;

    int e = s0;
    for (; e + 4 <= s1; e += 4) {
        int i0 = __ldg(&csr[e]);
        int i1 = __ldg(&csr[e + 1]);
        int i2 = __ldg(&csr[e + 2]);
        int i3 = __ldg(&csr[e + 3]);
        if constexpr (EDGE_SCALE) {
            float d0 = __ldg(&dis[i0]);
            float d1 = __ldg(&dis[i1]);
            float d2 = __ldg(&dis[i2]);
            float d3 = __ldg(&dis[i3]);
            vload_fma<VW>(base + (size_t)i0 * DOUT, d0, acc0);
            vload_fma<VW>(base + (size_t)i1 * DOUT, d1, acc1);
            vload_fma<VW>(base + (size_t)i2 * DOUT, d2, acc0);
            vload_fma<VW>(base + (size_t)i3 * DOUT, d3, acc1);
        } else {
            vload_add<VW>(base + (size_t)i0 * DOUT, acc0);
            vload_add<VW>(base + (size_t)i1 * DOUT, acc1);
            vload_add<VW>(base + (size_t)i2 * DOUT, acc0);
            vload_add<VW>(base + (size_t)i3 * DOUT, acc1);
        }
    }
    for (; e < s1; e++) {
        int i0 = __ldg(&csr[e]);
        if constexpr (EDGE_SCALE) {
            float d0 = __ldg(&dis[i0]);
            vload_fma<VW>(base + (size_t)i0 * DOUT, d0, acc0);
        } else {
            vload_add<VW>(base + (size_t)i0 * DOUT, acc0);
        }
    }

    float dv = dis[v];
    const float* hp = hs + (size_t)v * DOUT + fo;
    float* op = out + (size_t)v * DOUT + fo;
#pragma unroll
    for (int j = 0; j < VW; j++) {
        float self = EDGE_SCALE ? hp[j] * dv : hp[j];
        float r = dv * (acc0[j] + acc1[j] + self) + b[fo + j];
        op[j] = r > 0.0f ? r : 0.0f;
    }
}

// ---------------------------------------------------------------------------
__global__ void mlp_kernel(const float* __restrict__ x,
                           const float* __restrict__ lw0, const float* __restrict__ lb0,
                           const float* __restrict__ lw1, const float* __restrict__ lb1,
                           const float* __restrict__ lw2, const float* __restrict__ lb2,
                           float* __restrict__ s, int n) {
    __shared__ float w0[32 * 16], b0[16], w1[16 * 8], b1[8], w2[8], b2s[1];
    int t = threadIdx.x;
    for (int j = t; j < 32 * 16; j += blockDim.x) w0[j] = lw0[j];
    for (int j = t; j < 16; j += blockDim.x) b0[j] = lb0[j];
    for (int j = t; j < 16 * 8; j += blockDim.x) w1[j] = lw1[j];
    for (int j = t; j < 8; j += blockDim.x) b1[j] = lb1[j];
    for (int j = t; j < 8; j += blockDim.x) w2[j] = lw2[j];
    if (t == 0) b2s[0] = lb2[0];
    __syncthreads();

    int i = blockIdx.x * blockDim.x + t;
    if (i >= n) return;

    float xv[32];
#pragma unroll
    for (int k = 0; k < 32; k++) xv[k] = x[i * 32 + k];

    float y1[16];
#pragma unroll
    for (int j = 0; j < 16; j++) {
        float a = b0[j];
#pragma unroll
        for (int k = 0; k < 32; k++) a += xv[k] * w0[k * 16 + j];
        y1[j] = a > 0.0f ? a : 0.0f;
    }
    float y2[8];
#pragma unroll
    for (int j = 0; j < 8; j++) {
        float a = b1[j];
#pragma unroll
        for (int k = 0; k < 16; k++) a += y1[k] * w1[k * 8 + j];
        y2[j] = a > 0.0f ? a : 0.0f;
    }
    float z = b2s[0];
#pragma unroll
    for (int k = 0; k < 8; k++) z += y2[k] * w2[k];
    s[i] = 1.0f / (1.0f + expf(-z));
}

__global__ void edge_score_kernel(const int* __restrict__ pe,
                                  const float* __restrict__ s,
                                  float* __restrict__ out, int ep) {
    int i = blockIdx.x * blockDim.x + threadIdx.x;
    if (i < ep) {
        int2 p = ((const int2*)pe)[i];
        out[i] = s[p.x] * s[p.y];
    }
}

// ---------------------------------------------------------------------------
extern "C" void kernel_launch(void* const* d_in, const int* in_sizes, int n_in,
                              void* d_out, int out_size) {
    const float* x   = (const float*)d_in[0];
    const int* ei    = (const int*)d_in[1];
    const int* pe    = (const int*)d_in[2];
    const float* cw0 = (const float*)d_in[3];
    const float* cb0 = (const float*)d_in[4];
    const float* cw1 = (const float*)d_in[5];
    const float* cb1 = (const float*)d_in[6];
    const float* cw2 = (const float*)d_in[7];
    const float* cb2 = (const float*)d_in[8];
    const float* lw0 = (const float*)d_in[9];
    const float* lb0 = (const float*)d_in[10];
    const float* lw1 = (const float*)d_in[11];
    const float* lb1 = (const float*)d_in[12];
    const float* lw2 = (const float*)d_in[13];
    const float* lb2 = (const float*)d_in[14];
    float* out = (float*)d_out;

    const int N  = in_sizes[0] / 128;
    const int E  = in_sizes[1] / 2;
    const int EP = out_size;

    const int* src = ei;
    const int* dst = ei + E;

    float *hs, *xb, *dis, *sc;
    int *counts, *offsets, *cursor, *csr, *bsums;
    cudaGetSymbolAddress((void**)&hs, g_hs);
    cudaGetSymbolAddress((void**)&xb, g_x);
    cudaGetSymbolAddress((void**)&dis, g_dis);
    cudaGetSymbolAddress((void**)&sc, g_s);
    cudaGetSymbolAddress((void**)&counts, g_counts);
    cudaGetSymbolAddress((void**)&offsets, g_offsets);
    cudaGetSymbolAddress((void**)&cursor, g_cursor);
    cudaGetSymbolAddress((void**)&csr, g_csr);
    cudaGetSymbolAddress((void**)&bsums, g_bsums);

    // Lazy side-stream + events for capture-legal fork/join.
    static cudaStream_t s_side = nullptr;
    static cudaEvent_t ev_fork = nullptr, ev_join = nullptr;
    if (!s_side) {
        cudaStreamCreateWithFlags(&s_side, cudaStreamNonBlocking);
        cudaEventCreateWithFlags(&ev_fork, cudaEventDisableTiming);
        cudaEventCreateWithFlags(&ev_join, cudaEventDisableTiming);
    }

    const int B = 256;
    const int NB = (N + 255) / 256;
    const int E4 = (E + 3) / 4;
    int gwarp = (N * 32 + B - 1) / B;  // 1 warp per node

    // ---- fork: CSR build + dis on side stream, GEMM0 (unscaled) on main ----
    cudaEventRecord(ev_fork, 0);
    cudaStreamWaitEvent(s_side, ev_fork, 0);

    cudaMemsetAsync(counts, 0, N * sizeof(int), s_side);
    hist_kernel<<<(E4 + B - 1) / B, B, 0, s_side>>>(dst, E, counts);
    blocksum_kernel<<<NB, 256, 0, s_side>>>(counts, bsums, N);
    scan_bsums_kernel<<<1, 256, 0, s_side>>>(bsums, NB, offsets, N);
    offsets_kernel<<<NB, 256, 0, s_side>>>(counts, bsums, offsets, cursor, dis, N);
    fill_kernel<<<(E4 + B - 1) / B, B, 0, s_side>>>(src, dst, E, cursor, csr);
    cudaEventRecord(ev_join, s_side);

    // GEMM0 does not need dis (scale folded into gather-0's edge loop)
    gemm_scale_kernel<128, 128, false><<<(N + 127) / 128, 256>>>(x, cw0, nullptr, hs, N);

    cudaStreamWaitEvent(0, ev_join, 0);
    // ---- join ----

    // Layer 0: gather with per-edge dis scaling
    gather_combine_kernel<128, true><<<gwarp, B>>>(hs, csr, offsets, cb0, dis, xb, N);
    // Layer 1: 128 -> 64 (dis folded into GEMM epilogue)
    gemm_scale_kernel<128, 64, true><<<(N + 127) / 128, 256>>>(xb, cw1, dis, hs, N);
    gather_combine_kernel<64, false><<<gwarp, B>>>(hs, csr, offsets, cb1, dis, xb, N);
    // Layer 2: 64 -> 32
    gemm_scale_kernel<64, 32, true><<<(N + 127) / 128, 256>>>(xb, cw2, dis, hs, N);
    gather_combine_kernel<32, false><<<gwarp, B>>>(hs, csr, offsets, cb2, dis, xb, N);

    mlp_kernel<<<(N + B - 1) / B, B>>>(xb, lw0, lb0, lw1, lb1, lw2, lb2, sc, N);
    edge_score_kernel<<<(EP + B - 1) / B, B>>>(pe, sc, out, EP);
}

// round 12
// speedup vs baseline: 1.1585x; 1.0895x over previous
#include <cuda_runtime.h>
#include <cuda_fp16.h>
#include <math.h>

#define NMAX 50000
#define EMAX 800000
#define DMAX 128

// Scratch (device globals; no allocation in kernel_launch)
__device__ __half g_hs[NMAX * DMAX];   // h (= x@W) payload in fp16
__device__ float g_x[NMAX * DMAX];     // layer activations (fp32)
__device__ float g_dis[NMAX];          // rsqrt(deg+1)
__device__ float g_s[NMAX];            // node scores
__device__ int   g_counts[NMAX];       // in-degree histogram
__device__ int   g_offsets[NMAX + 1];  // CSR row offsets
__device__ int   g_cursor[NMAX];       // fill cursors
__device__ int   g_csr[EMAX];          // CSR src indices grouped by dst
__device__ int   g_bsums[256];         // scan block partials

// ---------------------------------------------------------------------------
// f32x2 packed-FMA helpers (sm_103a dual fp32 path)
__device__ __forceinline__ unsigned long long pack2(float x) {
    unsigned long long r;
    asm("mov.b64 %0, {%1, %1};" : "=l"(r) : "f"(x));
    return r;
}
__device__ __forceinline__ void fma2(unsigned long long& d,
                                     unsigned long long a,
                                     unsigned long long b) {
    asm("fma.rn.f32x2 %0, %1, %2, %3;" : "=l"(d) : "l"(a), "l"(b), "l"(d));
}
__device__ __forceinline__ float2 unpack2(unsigned long long v) {
    float2 f;
    asm("mov.b64 {%0, %1}, %2;" : "=f"(f.x), "=f"(f.y) : "l"(v));
    return f;
}

// ---------------------------------------------------------------------------
// Histogram, 4 edges per thread (int4)
__global__ void hist_kernel(const int* __restrict__ dst, int E, int* counts) {
    int i = blockIdx.x * blockDim.x + threadIdx.x;
    int E4 = E >> 2;
    if (i < E4) {
        int4 d = ((const int4*)dst)[i];
        atomicAdd(&counts[d.x], 1);
        atomicAdd(&counts[d.y], 1);
        atomicAdd(&counts[d.z], 1);
        atomicAdd(&counts[d.w], 1);
    }
    int t = E4 * 4 + i;
    if (i < (E & 3)) atomicAdd(&counts[dst[t]], 1);
}

// Two-level exclusive scan
__global__ void blocksum_kernel(const int* __restrict__ counts, int* bsums, int n) {
    __shared__ int sh[256];
    int i = blockIdx.x * 256 + threadIdx.x;
    sh[threadIdx.x] = (i < n) ? counts[i] : 0;
    __syncthreads();
#pragma unroll
    for (int off = 128; off > 0; off >>= 1) {
        if (threadIdx.x < off) sh[threadIdx.x] += sh[threadIdx.x + off];
        __syncthreads();
    }
    if (threadIdx.x == 0) bsums[blockIdx.x] = sh[0];
}

__global__ void scan_bsums_kernel(int* bsums, int nb, int* offsets, int n) {
    __shared__ int sh[256];
    int t = threadIdx.x;
    int v = (t < nb) ? bsums[t] : 0;
    sh[t] = v;
    __syncthreads();
#pragma unroll
    for (int off = 1; off < 256; off <<= 1) {
        int u = (t >= off) ? sh[t - off] : 0;
        __syncthreads();
        sh[t] += u;
        __syncthreads();
    }
    if (t < nb) bsums[t] = sh[t] - v;  // exclusive
    if (t == 255) offsets[n] = sh[255];
}

__global__ void offsets_kernel(const int* __restrict__ counts,
                               const int* __restrict__ bsums,
                               int* offsets, int* cursor, float* dis, int n) {
    __shared__ int sh[256];
    int t = threadIdx.x;
    int i = blockIdx.x * 256 + t;
    int v = (i < n) ? counts[i] : 0;
    sh[t] = v;
    __syncthreads();
#pragma unroll
    for (int off = 1; off < 256; off <<= 1) {
        int u = (t >= off) ? sh[t - off] : 0;
        __syncthreads();
        sh[t] += u;
        __syncthreads();
    }
    if (i < n) {
        int o = bsums[blockIdx.x] + sh[t] - v;
        offsets[i] = o;
        cursor[i] = o;
        dis[i] = rsqrtf((float)v + 1.0f);
    }
}

// CSR fill, 4 edges per thread
__global__ void fill_kernel(const int* __restrict__ src,
                            const int* __restrict__ dst, int E,
                            int* cursor, int* __restrict__ csr) {
    int i = blockIdx.x * blockDim.x + threadIdx.x;
    int E4 = E >> 2;
    if (i < E4) {
        int4 s = ((const int4*)src)[i];
        int4 d = ((const int4*)dst)[i];
        int p0 = atomicAdd(&cursor[d.x], 1);
        int p1 = atomicAdd(&cursor[d.y], 1);
        int p2 = atomicAdd(&cursor[d.z], 1);
        int p3 = atomicAdd(&cursor[d.w], 1);
        csr[p0] = s.x;
        csr[p1] = s.y;
        csr[p2] = s.z;
        csr[p3] = s.w;
    }
    int t = E4 * 4 + i;
    if (i < (E & 3)) {
        int pos = atomicAdd(&cursor[dst[t]], 1);
        csr[pos] = src[t];
    }
}

// ---------------------------------------------------------------------------
// Register-blocked SGEMM (f32x2 FMAs), fp32 accumulate, fp16 output.
// out[r, c] = half((A@W)[r, c] * (SCALE ? dis[r] : 1)).  BM=128, 256 threads.
template <int DIN, int DOUT, bool SCALE>
__global__ void gemm_scale_kernel(const float* __restrict__ A,
                                  const float* __restrict__ W,
                                  const float* __restrict__ dis,
                                  __half* __restrict__ out, int n) {
    constexpr int BM = 128, BK = 8, TN = 8;
    constexpr int TX = DOUT / TN;
    constexpr int TY = 256 / TX;
    constexpr int TM = BM / TY;

    __shared__ float As[BK][BM + 4];
    __shared__ float Ws[BK][DOUT];

    int tid = threadIdx.x;
    int tx = tid % TX, ty = tid / TX;
    int row0 = blockIdx.x * BM;

    unsigned long long acc[TM][TN / 2] = {};

    for (int k0 = 0; k0 < DIN; k0 += BK) {
        {
            int r = tid >> 1;
            int kk = (tid & 1) * 4;
            int grow = row0 + r;
            float4 v = make_float4(0.f, 0.f, 0.f, 0.f);
            if (grow < n) v = *(const float4*)&A[grow * DIN + k0 + kk];
            As[kk][r] = v.x;
            As[kk + 1][r] = v.y;
            As[kk + 2][r] = v.z;
            As[kk + 3][r] = v.w;
        }
        {
            const float4* wsrc = (const float4*)(W + k0 * DOUT);
            float4* wdst = (float4*)&Ws[0][0];
#pragma unroll
            for (int i = tid; i < BK * DOUT / 4; i += 256) wdst[i] = wsrc[i];
        }
        __syncthreads();

#pragma unroll
        for (int k = 0; k < BK; k++) {
            unsigned long long b2[TN / 2];
            const unsigned long long* wp =
                (const unsigned long long*)&Ws[k][tx * TN];
#pragma unroll
            for (int j = 0; j < TN / 2; j++) b2[j] = wp[j];
#pragma unroll
            for (int i = 0; i < TM; i++) {
                unsigned long long rp = pack2(As[k][ty * TM + i]);
#pragma unroll
                for (int j = 0; j < TN / 2; j++) fma2(acc[i][j], rp, b2[j]);
            }
        }
        __syncthreads();
    }

#pragma unroll
    for (int i = 0; i < TM; i++) {
        int r = row0 + ty * TM + i;
        if (r < n) {
            float dv = SCALE ? dis[r] : 1.0f;
            float2 p0 = unpack2(acc[i][0]);
            float2 p1 = unpack2(acc[i][1]);
            float2 p2 = unpack2(acc[i][2]);
            float2 p3 = unpack2(acc[i][3]);
            __half2 q0 = __float22half2_rn(make_float2(p0.x * dv, p0.y * dv));
            __half2 q1 = __float22half2_rn(make_float2(p1.x * dv, p1.y * dv));
            __half2 q2 = __float22half2_rn(make_float2(p2.x * dv, p2.y * dv));
            __half2 q3 = __float22half2_rn(make_float2(p3.x * dv, p3.y * dv));
            uint4 pk = make_uint4(*(unsigned*)&q0, *(unsigned*)&q1,
                                  *(unsigned*)&q2, *(unsigned*)&q3);
            *(uint4*)&out[r * DOUT + tx * TN] = pk;
        }
    }
}

// ---------------------------------------------------------------------------
// fp16 vector loads, fp32 accumulate.
template <int VW>
__device__ __forceinline__ void vload_add_h(const __half* __restrict__ p, float* a) {
    if constexpr (VW == 4) {
        uint2 u = *(const uint2*)p;
        float2 f0 = __half22float2(*(const __half2*)&u.x);
        float2 f1 = __half22float2(*(const __half2*)&u.y);
        a[0] += f0.x; a[1] += f0.y; a[2] += f1.x; a[3] += f1.y;
    } else if constexpr (VW == 2) {
        __half2 h = *(const __half2*)p;
        float2 f = __half22float2(h);
        a[0] += f.x; a[1] += f.y;
    } else {
        a[0] += __half2float(*p);
    }
}
template <int VW>
__device__ __forceinline__ void vload_fma_h(const __half* __restrict__ p, float s,
                                            float* a) {
    if constexpr (VW == 4) {
        uint2 u = *(const uint2*)p;
        float2 f0 = __half22float2(*(const __half2*)&u.x);
        float2 f1 = __half22float2(*(const __half2*)&u.y);
        a[0] += f0.x * s; a[1] += f0.y * s; a[2] += f1.x * s; a[3] += f1.y * s;
    } else if constexpr (VW == 2) {
        __half2 h = *(const __half2*)p;
        float2 f = __half22float2(h);
        a[0] += f.x * s; a[1] += f.y * s;
    } else {
        a[0] += __half2float(*p) * s;
    }
}

// One warp per node, edge loop unrolled x4, dual accumulators.
// EDGE_SCALE=false: hs = h*dis[row] (fp16); out = relu(dis[v]*(acc+hs[v]) + b)
// EDGE_SCALE=true:  hs = h (fp16); acc = sum h[src]*dis[src];
//   out = relu(dis[v]*(acc + h[v]*dis[v]) + b)
template <int DOUT, bool EDGE_SCALE>
__global__ void __launch_bounds__(256)
gather_combine_kernel(const __half* __restrict__ hs,
                      const int* __restrict__ csr,
                      const int* __restrict__ offsets,
                      const float* __restrict__ b,
                      const float* __restrict__ dis,
                      float* __restrict__ out, int n) {
    constexpr int VW = DOUT / 32;
    int warp = (blockIdx.x * blockDim.x + threadIdx.x) >> 5;
    int lane = threadIdx.x & 31;
    if (warp >= n) return;
    int v = warp;
    int s0 = offsets[v], s1 = offsets[v + 1];

    float acc0[VW] = {}, acc1[VW] = {};
    int fo = lane * VW;
    const __half* __restrict__ base = hs + fo;

    int e = s0;
    for (; e + 4 <= s1; e += 4) {
        int i0 = __ldg(&csr[e]);
        int i1 = __ldg(&csr[e + 1]);
        int i2 = __ldg(&csr[e + 2]);
        int i3 = __ldg(&csr[e + 3]);
        if constexpr (EDGE_SCALE) {
            float d0 = __ldg(&dis[i0]);
            float d1 = __ldg(&dis[i1]);
            float d2 = __ldg(&dis[i2]);
            float d3 = __ldg(&dis[i3]);
            vload_fma_h<VW>(base + (size_t)i0 * DOUT, d0, acc0);
            vload_fma_h<VW>(base + (size_t)i1 * DOUT, d1, acc1);
            vload_fma_h<VW>(base + (size_t)i2 * DOUT, d2, acc0);
            vload_fma_h<VW>(base + (size_t)i3 * DOUT, d3, acc1);
        } else {
            vload_add_h<VW>(base + (size_t)i0 * DOUT, acc0);
            vload_add_h<VW>(base + (size_t)i1 * DOUT, acc1);
            vload_add_h<VW>(base + (size_t)i2 * DOUT, acc0);
            vload_add_h<VW>(base + (size_t)i3 * DOUT, acc1);
        }
    }
    for (; e < s1; e++) {
        int i0 = __ldg(&csr[e]);
        if constexpr (EDGE_SCALE) {
            float d0 = __ldg(&dis[i0]);
            vload_fma_h<VW>(base + (size_t)i0 * DOUT, d0, acc0);
        } else {
            vload_add_h<VW>(base + (size_t)i0 * DOUT, acc0);
        }
    }

    float dv = dis[v];
    const __half* hp = hs + (size_t)v * DOUT + fo;
    float* op = out + (size_t)v * DOUT + fo;
    float self[VW];
    vload_add_h<VW>(hp, acc0);  // placeholder avoided; do explicit read below
    // undo: we must not add hp into acc0 blindly for EDGE_SCALE case
    // (handled by subtracting below is ugly) -- instead recompute:
#pragma unroll
    for (int j = 0; j < VW; j++) self[j] = 0.0f;
    // NOTE: the vload above already added unscaled hp into acc0 (correct for
    // EDGE_SCALE=false where self term is unscaled h*dis path). For
    // EDGE_SCALE=true we need h[v]*dv, so compensate:
    if constexpr (EDGE_SCALE) {
        // remove the unscaled contribution and add scaled one
        float tmp[VW] = {};
        vload_add_h<VW>(hp, tmp);
#pragma unroll
        for (int j = 0; j < VW; j++) acc0[j] += tmp[j] * dv - tmp[j];
    }
#pragma unroll
    for (int j = 0; j < VW; j++) {
        float r = dv * (acc0[j] + acc1[j] + self[j]) + b[fo + j];
        op[j] = r > 0.0f ? r : 0.0f;
    }
}

// ---------------------------------------------------------------------------
__global__ void mlp_kernel(const float* __restrict__ x,
                           const float* __restrict__ lw0, const float* __restrict__ lb0,
                           const float* __restrict__ lw1, const float* __restrict__ lb1,
                           const float* __restrict__ lw2, const float* __restrict__ lb2,
                           float* __restrict__ s, int n) {
    __shared__ float w0[32 * 16], b0[16], w1[16 * 8], b1[8], w2[8], b2s[1];
    int t = threadIdx.x;
    for (int j = t; j < 32 * 16; j += blockDim.x) w0[j] = lw0[j];
    for (int j = t; j < 16; j += blockDim.x) b0[j] = lb0[j];
    for (int j = t; j < 16 * 8; j += blockDim.x) w1[j] = lw1[j];
    for (int j = t; j < 8; j += blockDim.x) b1[j] = lb1[j];
    for (int j = t; j < 8; j += blockDim.x) w2[j] = lw2[j];
    if (t == 0) b2s[0] = lb2[0];
    __syncthreads();

    int i = blockIdx.x * blockDim.x + t;
    if (i >= n) return;

    float xv[32];
#pragma unroll
    for (int k = 0; k < 32; k++) xv[k] = x[i * 32 + k];

    float y1[16];
#pragma unroll
    for (int j = 0; j < 16; j++) {
        float a = b0[j];
#pragma unroll
        for (int k = 0; k < 32; k++) a += xv[k] * w0[k * 16 + j];
        y1[j] = a > 0.0f ? a : 0.0f;
    }
    float y2[8];
#pragma unroll
    for (int j = 0; j < 8; j++) {
        float a = b1[j];
#pragma unroll
        for (int k = 0; k < 16; k++) a += y1[k] * w1[k * 8 + j];
        y2[j] = a > 0.0f ? a : 0.0f;
    }
    float z = b2s[0];
#pragma unroll
    for (int k = 0; k < 8; k++) z += y2[k] * w2[k];
    s[i] = 1.0f / (1.0f + expf(-z));
}

__global__ void edge_score_kernel(const int* __restrict__ pe,
                                  const float* __restrict__ s,
                                  float* __restrict__ out, int ep) {
    int i = blockIdx.x * blockDim.x + threadIdx.x;
    if (i < ep) {
        int2 p = ((const int2*)pe)[i];
        out[i] = s[p.x] * s[p.y];
    }
}

// ---------------------------------------------------------------------------
extern "C" void kernel_launch(void* const* d_in, const int* in_sizes, int n_in,
                              void* d_out, int out_size) {
    const float* x   = (const float*)d_in[0];
    const int* ei    = (const int*)d_in[1];
    const int* pe    = (const int*)d_in[2];
    const float* cw0 = (const float*)d_in[3];
    const float* cb0 = (const float*)d_in[4];
    const float* cw1 = (const float*)d_in[5];
    const float* cb1 = (const float*)d_in[6];
    const float* cw2 = (const float*)d_in[7];
    const float* cb2 = (const float*)d_in[8];
    const float* lw0 = (const float*)d_in[9];
    const float* lb0 = (const float*)d_in[10];
    const float* lw1 = (const float*)d_in[11];
    const float* lb1 = (const float*)d_in[12];
    const float* lw2 = (const float*)d_in[13];
    const float* lb2 = (const float*)d_in[14];
    float* out = (float*)d_out;

    const int N  = in_sizes[0] / 128;
    const int E  = in_sizes[1] / 2;
    const int EP = out_size;

    const int* src = ei;
    const int* dst = ei + E;

    float *xb, *dis, *sc;
    __half* hs;
    int *counts, *offsets, *cursor, *csr, *bsums;
    cudaGetSymbolAddress((void**)&hs, g_hs);
    cudaGetSymbolAddress((void**)&xb, g_x);
    cudaGetSymbolAddress((void**)&dis, g_dis);
    cudaGetSymbolAddress((void**)&sc, g_s);
    cudaGetSymbolAddress((void**)&counts, g_counts);
    cudaGetSymbolAddress((void**)&offsets, g_offsets);
    cudaGetSymbolAddress((void**)&cursor, g_cursor);
    cudaGetSymbolAddress((void**)&csr, g_csr);
    cudaGetSymbolAddress((void**)&bsums, g_bsums);

    // Lazy side-stream + events for capture-legal fork/join.
    static cudaStream_t s_side = nullptr;
    static cudaEvent_t ev_fork = nullptr, ev_join = nullptr;
    if (!s_side) {
        cudaStreamCreateWithFlags(&s_side, cudaStreamNonBlocking);
        cudaEventCreateWithFlags(&ev_fork, cudaEventDisableTiming);
        cudaEventCreateWithFlags(&ev_join, cudaEventDisableTiming);
    }

    const int B = 256;
    const int NB = (N + 255) / 256;
    const int E4 = (E + 3) / 4;
    int gwarp = (N * 32 + B - 1) / B;  // 1 warp per node

    // ---- fork: CSR build + dis on side stream, GEMM0 (unscaled) on main ----
    cudaEventRecord(ev_fork, 0);
    cudaStreamWaitEvent(s_side, ev_fork, 0);

    cudaMemsetAsync(counts, 0, N * sizeof(int), s_side);
    hist_kernel<<<(E4 + B - 1) / B, B, 0, s_side>>>(dst, E, counts);
    blocksum_kernel<<<NB, 256, 0, s_side>>>(counts, bsums, N);
    scan_bsums_kernel<<<1, 256, 0, s_side>>>(bsums, NB, offsets, N);
    offsets_kernel<<<NB, 256, 0, s_side>>>(counts, bsums, offsets, cursor, dis, N);
    fill_kernel<<<(E4 + B - 1) / B, B, 0, s_side>>>(src, dst, E, cursor, csr);
    cudaEventRecord(ev_join, s_side);

    // GEMM0 does not need dis (scale folded into gather-0's edge loop)
    gemm_scale_kernel<128, 128, false><<<(N + 127) / 128, 256>>>(x, cw0, nullptr, hs, N);

    cudaStreamWaitEvent(0, ev_join, 0);
    // ---- join ----

    // Layer 0: gather with per-edge dis scaling
    gather_combine_kernel<128, true><<<gwarp, B>>>(hs, csr, offsets, cb0, dis, xb, N);
    // Layer 1: 128 -> 64 (dis folded into GEMM epilogue)
    gemm_scale_kernel<128, 64, true><<<(N + 127) / 128, 256>>>(xb, cw1, dis, hs, N);
    gather_combine_kernel<64, false><<<gwarp, B>>>(hs, csr, offsets, cb1, dis, xb, N);
    // Layer 2: 64 -> 32
    gemm_scale_kernel<64, 32, true><<<(N + 127) / 128, 256>>>(xb, cw2, dis, hs, N);
    gather_combine_kernel<32, false><<<gwarp, B>>>(hs, csr, offsets, cb2, dis, xb, N);

    mlp_kernel<<<(N + B - 1) / B, B>>>(xb, lw0, lb0, lw1, lb1, lw2, lb2, sc, N);
    edge_score_kernel<<<(EP + B - 1) / B, B>>>(pe, sc, out, EP);
}